// round 3
// baseline (speedup 1.0000x reference)
#include <cuda_runtime.h>

#define B_   32
#define S_   1024
#define E_   64
#define H_   4
#define HD_  16
#define HID_ 256
#define AD_  32
#define NS_  64
#define TOPK_ 8
#define NTOK (B_*S_)

// scratch (alloc-free workaround: __device__ globals)
__device__ float g_q[NTOK*E_];
__device__ float g_k[NTOK*E_];
__device__ float g_v[NTOK*E_];
__device__ float g_av[NTOK*E_];
__device__ float g_x2[NTOK*E_];

// ---------------------------------------------------------------------------
// K1: rmsnorm + QKV projection.  grid=1024, block=256 (4 tokens/iter, 8 iters)
// dynamic smem: transposed padded wq/wk/wv (stride 65)
// ---------------------------------------------------------------------------
__global__ void qkv_kernel(const float* __restrict__ x, const float* __restrict__ nw,
                           const float* __restrict__ wq, const float* __restrict__ wk,
                           const float* __restrict__ wv) {
    extern __shared__ float dynq[];
    float* swq = dynq;               // 64*65
    float* swk = dynq + 4160;
    float* swv = dynq + 8320;
    __shared__ float sh[4][E_];
    __shared__ float swsum[8];

    int tid = threadIdx.x;
    for (int idx = tid; idx < E_*E_; idx += 256) {
        int e = idx >> 6, i = idx & 63;
        swq[i*65+e] = wq[idx];
        swk[i*65+e] = wk[idx];
        swv[i*65+e] = wv[idx];
    }
    __syncthreads();

    int g = tid >> 6, lane = tid & 63, wid = tid >> 5;
    int t0 = blockIdx.x * 32;
    for (int it = 0; it < 8; it++) {
        int t = t0 + it*4 + g;
        float xv = x[t*E_ + lane];
        // rmsnorm: sum of squares over 64 (2 warps per group)
        float ss = xv * xv;
#pragma unroll
        for (int o = 16; o > 0; o >>= 1) ss += __shfl_xor_sync(0xffffffffu, ss, o);
        if ((tid & 31) == 0) swsum[wid] = ss;
        __syncthreads();
        float tot = swsum[2*g] + swsum[2*g+1];
        float h = xv * rsqrtf(tot * (1.f/64.f) + 1e-5f) * nw[lane];
        sh[g][lane] = h;
        __syncthreads();

        float aq = 0.f, ak = 0.f, av = 0.f;
#pragma unroll 16
        for (int i = 0; i < E_; i++) {
            float hv = sh[g][i];
            aq = fmaf(hv, swq[i*65+lane], aq);
            ak = fmaf(hv, swk[i*65+lane], ak);
            av = fmaf(hv, swv[i*65+lane], av);
        }
        g_q[t*E_+lane] = aq;
        g_k[t*E_+lane] = ak;
        g_v[t*E_+lane] = av;
        __syncthreads();
    }
}

// ---------------------------------------------------------------------------
// K2: causal flash attention.  grid = B*H*(S/128)=1024, block=128.
// one query per thread, online softmax, K/V tiles in smem (broadcast reads)
// ---------------------------------------------------------------------------
__global__ void attn_kernel() {
    __shared__ float sK[128*HD_];
    __shared__ float sV[128*HD_];
    int qt = blockIdx.x & 7;
    int bh = blockIdx.x >> 3;
    int b = bh >> 2, h = bh & 3;
    int t = threadIdx.x;
    int qrow = qt*128 + t;

    const float* qp = g_q + ((size_t)(b*S_ + qrow)*E_ + h*HD_);
    float4 q0 = ((const float4*)qp)[0];
    float4 q1 = ((const float4*)qp)[1];
    float4 q2 = ((const float4*)qp)[2];
    float4 q3 = ((const float4*)qp)[3];

    float m = -1e30f, l = 0.f;
    float acc[HD_];
#pragma unroll
    for (int d = 0; d < HD_; d++) acc[d] = 0.f;

    for (int kt = 0; kt <= qt; kt++) {
        const float4* kp = (const float4*)(g_k + ((size_t)(b*S_ + kt*128 + t)*E_ + h*HD_));
        const float4* vp = (const float4*)(g_v + ((size_t)(b*S_ + kt*128 + t)*E_ + h*HD_));
#pragma unroll
        for (int d = 0; d < 4; d++) {
            ((float4*)sK)[t*4+d] = kp[d];
            ((float4*)sV)[t*4+d] = vp[d];
        }
        __syncthreads();
        int jmax = (kt == qt) ? (t + 1) : 128;
        for (int j = 0; j < jmax; j++) {
            const float4* kr = (const float4*)(sK + j*HD_);
            float4 k0 = kr[0], k1 = kr[1], k2 = kr[2], k3 = kr[3];
            float s = q0.x*k0.x;
            s = fmaf(q0.y,k0.y,s); s = fmaf(q0.z,k0.z,s); s = fmaf(q0.w,k0.w,s);
            s = fmaf(q1.x,k1.x,s); s = fmaf(q1.y,k1.y,s); s = fmaf(q1.z,k1.z,s); s = fmaf(q1.w,k1.w,s);
            s = fmaf(q2.x,k2.x,s); s = fmaf(q2.y,k2.y,s); s = fmaf(q2.z,k2.z,s); s = fmaf(q2.w,k2.w,s);
            s = fmaf(q3.x,k3.x,s); s = fmaf(q3.y,k3.y,s); s = fmaf(q3.z,k3.z,s); s = fmaf(q3.w,k3.w,s);
            s *= 0.25f;   // 1/sqrt(16)
            float mn = fmaxf(m, s);
            float corr = __expf(m - mn);
            float p = __expf(s - mn);
            l = l*corr + p;
            m = mn;
            const float4* vr = (const float4*)(sV + j*HD_);
            float4 v0 = vr[0], v1 = vr[1], v2 = vr[2], v3 = vr[3];
            acc[0]=fmaf(p,v0.x,acc[0]*corr);  acc[1]=fmaf(p,v0.y,acc[1]*corr);
            acc[2]=fmaf(p,v0.z,acc[2]*corr);  acc[3]=fmaf(p,v0.w,acc[3]*corr);
            acc[4]=fmaf(p,v1.x,acc[4]*corr);  acc[5]=fmaf(p,v1.y,acc[5]*corr);
            acc[6]=fmaf(p,v1.z,acc[6]*corr);  acc[7]=fmaf(p,v1.w,acc[7]*corr);
            acc[8]=fmaf(p,v2.x,acc[8]*corr);  acc[9]=fmaf(p,v2.y,acc[9]*corr);
            acc[10]=fmaf(p,v2.z,acc[10]*corr); acc[11]=fmaf(p,v2.w,acc[11]*corr);
            acc[12]=fmaf(p,v3.x,acc[12]*corr); acc[13]=fmaf(p,v3.y,acc[13]*corr);
            acc[14]=fmaf(p,v3.z,acc[14]*corr); acc[15]=fmaf(p,v3.w,acc[15]*corr);
        }
        __syncthreads();
    }
    float inv = 1.f / l;
    float* op = g_av + ((size_t)(b*S_ + qrow)*E_ + h*HD_);
#pragma unroll
    for (int d = 0; d < HD_; d++) op[d] = acc[d] * inv;
}

// ---------------------------------------------------------------------------
// K3: wo-proj + residual, rmsnorm, memory read (topk=8 of 64), mem_out + residual
// grid=1024 (32 tokens/block, same batch b), block=256 (4 token-groups of 64)
// address L2-norm folded into the smem-fill phase (redundant per block, ~free)
// ---------------------------------------------------------------------------
__global__ void mem_kernel(const float* __restrict__ x, const float* __restrict__ wo,
                           const float* __restrict__ mnw, const float* __restrict__ memq,
                           const float* __restrict__ memout, const float* __restrict__ mvals,
                           const float* __restrict__ maddr) {
    extern __shared__ float dynm[];
    float* swoT = dynm;              // 64*65
    float* smoT = swoT + 4160;       // 64*65
    float* smqT = smoT + 4160;       // 64*33
    float* saT  = smqT + 2112;       // 32*65  (normalized addresses, transposed)
    float* smv  = saT  + 2080;       // 64*64
    __shared__ float sav[4][E_], shh[4][E_], sq[4][AD_], ssc[4][NS_], se[4][NS_], srv[4][E_];
    __shared__ float swsum[8];
    __shared__ float sainv[NS_];

    int tid = threadIdx.x;
    int t0 = blockIdx.x * 32;
    int b = t0 / S_;

    // address norms (threads 0..63, one slot each)
    if (tid < NS_) {
        float s = 0.f;
#pragma unroll
        for (int a = 0; a < AD_; a++) { float v = maddr[tid*AD_+a]; s = fmaf(v, v, s); }
        sainv[tid] = 1.f / fmaxf(sqrtf(s), 1e-12f);
    }
    for (int idx = tid; idx < E_*E_; idx += 256) {
        int e = idx >> 6, i = idx & 63;
        swoT[i*65+e] = wo[idx];
        smoT[i*65+e] = memout[idx];
        smv[idx] = mvals[(size_t)b*NS_*E_ + idx];   // [n][e]
    }
    for (int idx = tid; idx < AD_*E_; idx += 256) {
        int a = idx >> 6, i = idx & 63;             // memq[a][i]
        smqT[i*33+a] = memq[idx];
    }
    __syncthreads();
    for (int idx = tid; idx < NS_*AD_; idx += 256) {
        int n = idx >> 5, a = idx & 31;
        saT[a*65+n] = maddr[idx] * sainv[n];
    }
    __syncthreads();

    int g = tid >> 6, lane = tid & 63, wid = tid >> 5;
    for (int it = 0; it < 8; it++) {
        int t = t0 + it*4 + g;
        sav[g][lane] = g_av[t*E_+lane];
        __syncthreads();
        // x1 = x + av @ wo.T
        float x1 = x[t*E_+lane];
#pragma unroll 16
        for (int i = 0; i < E_; i++) x1 = fmaf(sav[g][i], swoT[i*65+lane], x1);
        // rmsnorm
        float ss = x1 * x1;
#pragma unroll
        for (int o = 16; o > 0; o >>= 1) ss += __shfl_xor_sync(0xffffffffu, ss, o);
        if ((tid & 31) == 0) swsum[wid] = ss;
        __syncthreads();
        float tot = swsum[2*g] + swsum[2*g+1];
        float h = x1 * rsqrtf(tot * (1.f/64.f) + 1e-5f) * mnw[lane];
        shh[g][lane] = h;
        __syncthreads();
        // queries (AD=32) + l2norm : lower warp of each group
        if (lane < 32) {
            float qa = 0.f;
#pragma unroll 16
            for (int i = 0; i < E_; i++) qa = fmaf(shh[g][i], smqT[i*33+lane], qa);
            float nn = qa * qa;
#pragma unroll
            for (int o = 16; o > 0; o >>= 1) nn += __shfl_xor_sync(0xffffffffu, nn, o);
            sq[g][lane] = qa / fmaxf(sqrtf(nn), 1e-12f);
        }
        __syncthreads();
        // scores (64 slots) vs normalized addresses
        float sc = 0.f;
#pragma unroll
        for (int a = 0; a < AD_; a++) sc = fmaf(sq[g][a], saT[a*65+lane], sc);
        sc *= 4.0f;   // 1/TEMP
        ssc[g][lane] = sc;
        __syncthreads();
        // branchless top-8 by rank (ties -> lower index first, matches lax.top_k)
        int cnt = 0;
#pragma unroll 16
        for (int mi = 0; mi < NS_; mi++) {
            float sm = ssc[g][mi];
            cnt += (sm > sc) || (sm == sc && mi < lane);
        }
        bool sel = cnt < TOPK_;
        // global max (== max of selected set)
        float mr = sc;
#pragma unroll
        for (int o = 16; o > 0; o >>= 1) mr = fmaxf(mr, __shfl_xor_sync(0xffffffffu, mr, o));
        if ((tid & 31) == 0) swsum[wid] = mr;
        __syncthreads();
        float mx = fmaxf(swsum[2*g], swsum[2*g+1]);
        float ev = sel ? __expf(sc - mx) : 0.f;
        se[g][lane] = ev;
        float zr = ev;
#pragma unroll
        for (int o = 16; o > 0; o >>= 1) zr += __shfl_xor_sync(0xffffffffu, zr, o);
        __syncthreads();
        if ((tid & 31) == 0) swsum[wid] = zr;
        __syncthreads();
        float Zinv = 1.f / (swsum[2*g] + swsum[2*g+1]);
        // read_vals[e] = sum_n w_n * mv[b][n][e]
        float rv = 0.f;
#pragma unroll 16
        for (int n = 0; n < NS_; n++) rv = fmaf(se[g][n], smv[n*E_+lane], rv);
        rv *= Zinv;
        srv[g][lane] = rv;
        __syncthreads();
        // x2 = x1 + read_vals @ mem_out.T
        float o2 = x1;
#pragma unroll 16
        for (int i = 0; i < E_; i++) o2 = fmaf(srv[g][i], smoT[i*65+lane], o2);
        g_x2[t*E_+lane] = o2;
        __syncthreads();
    }
}

// ---------------------------------------------------------------------------
// K4: FFN (rmsnorm -> 256 gelu -> 64) + residual.  grid=512 (64 tokens/block),
// block=256, register-tiled: 8 tokens per iter, float4 weight loads.
// ---------------------------------------------------------------------------
__global__ void ffn_kernel(const float* __restrict__ fnw, const float* __restrict__ w1,
                           const float* __restrict__ b1, const float* __restrict__ w2,
                           const float* __restrict__ b2, float* __restrict__ out) {
    extern __shared__ float dynf[];
    float* sw1p = dynf;                 // [256][68]
    float* sw2p = dynf + 256*68;        // [64][260]
    __shared__ float sht[8][68];
    __shared__ float shid[8][HID_];

    int tid = threadIdx.x;
    for (int idx = tid; idx < HID_*E_; idx += 256) {
        int j = idx >> 6, i = idx & 63;
        sw1p[j*68+i] = w1[idx];
    }
    for (int idx = tid; idx < E_*HID_; idx += 256) {
        int e = idx >> 8, j = idx & 255;
        sw2p[e*260+j] = w2[idx];
    }
    __syncthreads();

    int t0 = blockIdx.x * 64;
    int w = tid >> 5, ln = tid & 31;
    int e = tid & 63, tp = tid >> 6;
    float bj = b1[tid];
    float bb = b2[e];

    for (int it = 0; it < 8; it++) {
        int tb = t0 + it*8;
        // rmsnorm: warp w handles token tb+w (64 elems, 2 per lane)
        {
            int t = tb + w;
            float x0 = g_x2[t*E_ + ln];
            float x1v = g_x2[t*E_ + 32 + ln];
            float ssq = fmaf(x0, x0, x1v*x1v);
#pragma unroll
            for (int o = 16; o > 0; o >>= 1) ssq += __shfl_xor_sync(0xffffffffu, ssq, o);
            float r = rsqrtf(ssq * (1.f/64.f) + 1e-5f);
            sht[w][ln]      = x0 * r * fnw[ln];
            sht[w][32+ln]   = x1v * r * fnw[32+ln];
        }
        __syncthreads();
        // hid: thread = hidden unit j (0..255), 8 tokens
        float acc[8];
#pragma unroll
        for (int k = 0; k < 8; k++) acc[k] = bj;
#pragma unroll 4
        for (int i = 0; i < E_; i += 4) {
            float4 wv = *(const float4*)(sw1p + tid*68 + i);
#pragma unroll
            for (int k = 0; k < 8; k++) {
                float4 hv = *(const float4*)(&sht[k][i]);
                acc[k] = fmaf(hv.x, wv.x, acc[k]);
                acc[k] = fmaf(hv.y, wv.y, acc[k]);
                acc[k] = fmaf(hv.z, wv.z, acc[k]);
                acc[k] = fmaf(hv.w, wv.w, acc[k]);
            }
        }
#pragma unroll
        for (int k = 0; k < 8; k++) {
            float v = acc[k];
            shid[k][tid] = 0.5f * v * (1.f + erff(v * 0.70710678118654752f));
        }
        __syncthreads();
        // out: thread handles output e for tokens 2*tp and 2*tp+1
        float o0 = 0.f, o1 = 0.f;
#pragma unroll 8
        for (int j = 0; j < HID_; j += 4) {
            float4 wv = *(const float4*)(sw2p + e*260 + j);
            float4 h0 = *(const float4*)(&shid[2*tp][j]);
            float4 h1 = *(const float4*)(&shid[2*tp+1][j]);
            o0 = fmaf(h0.x, wv.x, o0); o0 = fmaf(h0.y, wv.y, o0);
            o0 = fmaf(h0.z, wv.z, o0); o0 = fmaf(h0.w, wv.w, o0);
            o1 = fmaf(h1.x, wv.x, o1); o1 = fmaf(h1.y, wv.y, o1);
            o1 = fmaf(h1.z, wv.z, o1); o1 = fmaf(h1.w, wv.w, o1);
        }
        int ta = tb + 2*tp, tc = ta + 1;
        out[ta*E_+e] = g_x2[ta*E_+e] + o0 + bb;
        out[tc*E_+e] = g_x2[tc*E_+e] + o1 + bb;
        __syncthreads();
    }
}

// ---------------------------------------------------------------------------
extern "C" void kernel_launch(void* const* d_in, const int* in_sizes, int n_in,
                              void* d_out, int out_size) {
    const float* x      = (const float*)d_in[0];
    const float* maddr  = (const float*)d_in[1];
    const float* mvals  = (const float*)d_in[2];
    const float* anw    = (const float*)d_in[3];
    const float* wq     = (const float*)d_in[4];
    const float* wk     = (const float*)d_in[5];
    const float* wv     = (const float*)d_in[6];
    const float* wo     = (const float*)d_in[7];
    const float* mnw    = (const float*)d_in[8];
    const float* memq   = (const float*)d_in[9];
    const float* memout = (const float*)d_in[10];
    const float* fnw    = (const float*)d_in[11];
    const float* w1     = (const float*)d_in[12];
    const float* b1     = (const float*)d_in[13];
    const float* w2     = (const float*)d_in[14];
    const float* b2     = (const float*)d_in[15];
    float* out = (float*)d_out;

    cudaFuncSetAttribute(qkv_kernel, cudaFuncAttributeMaxDynamicSharedMemorySize, 12480*4);
    cudaFuncSetAttribute(mem_kernel, cudaFuncAttributeMaxDynamicSharedMemorySize, 16608*4);
    cudaFuncSetAttribute(ffn_kernel, cudaFuncAttributeMaxDynamicSharedMemorySize, (256*68+64*260)*4);

    qkv_kernel<<<1024, 256, 12480*4>>>(x, anw, wq, wk, wv);
    attn_kernel<<<1024, 128>>>();
    mem_kernel<<<1024, 256, 16608*4>>>(x, wo, mnw, memq, memout, mvals, maddr);
    ffn_kernel<<<512, 256, (256*68+64*260)*4>>>(fnw, w1, b1, w2, b2, out);
}